// round 3
// baseline (speedup 1.0000x reference)
#include <cuda_runtime.h>
#include <cuda_bf16.h>

#define B_ 512
#define T_ 512
#define N_ 64

#define L2E 1.4426950408889634f   // log2(e)
#define LN2 0.6931471805599453f   // ln(2)

// ---- packed f32x2 + MUFU helpers (sm_103a) ----
__device__ __forceinline__ void ffma2(unsigned long long &d,
                                      unsigned long long a,
                                      unsigned long long b) {
    asm("fma.rn.f32x2 %0, %1, %2, %0;" : "+l"(d) : "l"(a), "l"(b));
}
__device__ __forceinline__ unsigned long long fadd2(unsigned long long a,
                                                    unsigned long long b) {
    unsigned long long d;
    asm("add.rn.f32x2 %0, %1, %2;" : "=l"(d) : "l"(a), "l"(b));
    return d;
}
__device__ __forceinline__ unsigned long long pack2(float lo, float hi) {
    unsigned long long d;
    asm("mov.b64 %0, {%1, %2};" : "=l"(d) : "f"(lo), "f"(hi));
    return d;
}
__device__ __forceinline__ void unpack2(unsigned long long v, float &lo, float &hi) {
    asm("mov.b64 {%0, %1}, %2;" : "=f"(lo), "=f"(hi) : "l"(v));
}
__device__ __forceinline__ float ex2(float x) {
    float r; asm("ex2.approx.f32 %0, %1;" : "=f"(r) : "f"(x)); return r;
}
__device__ __forceinline__ float lg2(float x) {
    float r; asm("lg2.approx.f32 %0, %1;" : "=f"(r) : "f"(x)); return r;
}

// ONE WARP per batch element; no __syncthreads in the recursion.
// Thread k owns tag-columns (2k, 2k+1); holds exp2(trans2[:, col]) for both
// columns in 64 packed f32x2 registers (packed over the i dimension).
//
// Everything runs in log2 units: a2 = alpha * log2(e), trans2 = trans * log2(e),
// emit2 = emit * log2(e). Recursion:
//   E[i]   = ex2(a2[i] - r)        r = previous step's a2[0] (common shift,
//                                  shfl'd one step early -> latency hidden)
//   s_c    = sum_i E[i] * ET2[i][c]          (packed f32x2 GEMV)
//   a2'[c] = emit2[t][c] + lg2(s_c) ; Mt += r
// One STS.64 + one __syncwarp + 16 broadcast LDS.128 + 64 FFMA2 per step.
__global__ __launch_bounds__(64) void crf_fwd(
    const float* __restrict__ inputs,   // [B, T, N]
    const float* __restrict__ trans,    // [N, N]
    const int*   __restrict__ tags,     // [B, T]
    const int*   __restrict__ lens,     // [B]
    float*       __restrict__ out)      // [B + N*N]
{
    const int warp = threadIdx.x >> 5;
    const int lane = threadIdx.x & 31;
    const int b    = blockIdx.x * 2 + warp;   // grid = 256 blocks, 2 warps each
    const int c0   = 2 * lane;                // owned columns c0, c0+1

    // Per-warp double-buffered E vector (68-float rows keep 16B alignment).
    __shared__ float Esh[2][2][68];

    // Passthrough copy of transition_params: 256 blocks x 16 floats.
    if (threadIdx.x < 4) {
        const int idx = blockIdx.x * 4 + threadIdx.x;     // float4 index
        reinterpret_cast<float4*>(out + B_)[idx] =
            reinterpret_cast<const float4*>(trans)[idx];
    }

    // Register-resident ET2[i][c] = exp2(trans[i][c] * L2E), packed over i.
    unsigned long long ETa[32], ETb[32];
#pragma unroll
    for (int m = 0; m < 32; m++) {
        const float2 t0 = *reinterpret_cast<const float2*>(&trans[(2 * m) * N_ + c0]);
        const float2 t1 = *reinterpret_cast<const float2*>(&trans[(2 * m + 1) * N_ + c0]);
        ETa[m] = pack2(ex2(t0.x * L2E), ex2(t1.x * L2E));
        ETb[m] = pack2(ex2(t0.y * L2E), ex2(t1.y * L2E));
    }

    const float* emit = inputs + (size_t)b * T_ * N_;
    const int len = lens[b];
    const int steps = (len > 1) ? (len - 1) : 0;

    // t = 0 alphas in log2 units.
    const float2 e0 = *reinterpret_cast<const float2*>(&emit[c0]);
    float aLo = e0.x * L2E;
    float aHi = e0.y * L2E;
    float Mt = 0.0f;                        // accumulated shift (log2 units)
    float r  = __shfl_sync(0xffffffffu, aLo, 0);   // first rebase shift

    // Prefetch emissions (distance 2), pre-scaled to log2 units.
    float2 ec = make_float2(0.f, 0.f), en = make_float2(0.f, 0.f);
    if (steps >= 1) { const float2 v = *reinterpret_cast<const float2*>(&emit[N_ + c0]);
                      ec.x = v.x * L2E; ec.y = v.y * L2E; }
    if (steps >= 2) { const float2 v = *reinterpret_cast<const float2*>(&emit[2 * N_ + c0]);
                      en.x = v.x * L2E; en.y = v.y * L2E; }

    for (int t = 1; t <= steps; t++) {
        float2 enn = make_float2(0.f, 0.f);
        if (t + 2 <= steps) {
            const float2 v = *reinterpret_cast<const float2*>(&emit[(t + 2) * N_ + c0]);
            enn.x = v.x * L2E; enn.y = v.y * L2E;
        }
        const int buf = t & 1;

        // E pair -> smem (one STS.64), warp-local sync only.
        const float eL = ex2(aLo - r);
        const float eH = ex2(aHi - r);
        *reinterpret_cast<float2*>(&Esh[warp][buf][c0]) = make_float2(eL, eH);
        Mt += r;
        __syncwarp();

        // GEMV for both owned columns: 16 broadcast LDS.128 + 64 FFMA2.
        const ulonglong2* ev = reinterpret_cast<const ulonglong2*>(&Esh[warp][buf][0]);
        unsigned long long b0 = 0ull, b1 = 0ull, b2 = 0ull, b3 = 0ull;
        unsigned long long d0 = 0ull, d1 = 0ull, d2 = 0ull, d3 = 0ull;
#pragma unroll
        for (int m = 0; m < 8; m++) {
            const ulonglong2 p = ev[2 * m];        // E[8m..8m+3]
            const ulonglong2 q = ev[2 * m + 1];    // E[8m+4..8m+7]
            ffma2(b0, p.x, ETa[4 * m + 0]);
            ffma2(b1, p.y, ETa[4 * m + 1]);
            ffma2(b2, q.x, ETa[4 * m + 2]);
            ffma2(b3, q.y, ETa[4 * m + 3]);
            ffma2(d0, p.x, ETb[4 * m + 0]);
            ffma2(d1, p.y, ETb[4 * m + 1]);
            ffma2(d2, q.x, ETb[4 * m + 2]);
            ffma2(d3, q.y, ETb[4 * m + 3]);
        }
        float sl0, sh0, sl1, sh1;
        unpack2(fadd2(fadd2(b0, b1), fadd2(b2, b3)), sl0, sh0);
        unpack2(fadd2(fadd2(d0, d1), fadd2(d2, d3)), sl1, sh1);

        aLo = ec.x + lg2(sl0 + sh0);
        aHi = ec.y + lg2(sl1 + sh1);
        r = __shfl_sync(0xffffffffu, aLo, 0);   // next step's shift (latency hidden)
        ec = en;
        en = enn;
        // Double buffering: next iteration writes the other buffer; the
        // __syncwarp inside each step orders reuse two steps later.
    }

    // logZ = (Mt + log2-sumexp2 over final local alphas) * ln2.
    float m = fmaxf(aLo, aHi);
#pragma unroll
    for (int off = 16; off; off >>= 1)
        m = fmaxf(m, __shfl_xor_sync(0xffffffffu, m, off));
    float s = ex2(aLo - m) + ex2(aHi - m);
#pragma unroll
    for (int off = 16; off; off >>= 1)
        s += __shfl_xor_sync(0xffffffffu, s, off);
    const float logZ = (Mt + m + lg2(s)) * LN2;

    // Sequence score (raw/natural units), strided over 32 lanes.
    const int* btags = tags + b * T_;
    float sc = 0.0f;
    for (int t = lane; t < len; t += 32)
        sc += emit[t * N_ + btags[t]];
    for (int t = lane + 1; t < len; t += 32)
        sc += trans[btags[t - 1] * N_ + btags[t]];
#pragma unroll
    for (int off = 16; off; off >>= 1)
        sc += __shfl_xor_sync(0xffffffffu, sc, off);

    if (lane == 0) out[b] = sc - logZ;
}

extern "C" void kernel_launch(void* const* d_in, const int* in_sizes, int n_in,
                              void* d_out, int out_size) {
    const float* inputs = (const float*)d_in[0];   // [512, 512, 64] f32
    const float* trans  = (const float*)d_in[1];   // [64, 64] f32
    const int*   tags   = (const int*)d_in[2];     // [512, 512] i32
    const int*   lens   = (const int*)d_in[3];     // [512] i32
    float*       out    = (float*)d_out;           // [512 + 4096] f32

    crf_fwd<<<B_ / 2, 64>>>(inputs, trans, tags, lens, out);
}

// round 4
// speedup vs baseline: 2.5639x; 2.5639x over previous
#include <cuda_runtime.h>
#include <cuda_bf16.h>

#define B_ 512
#define T_ 512
#define N_ 64

#define L2E 1.4426950408889634f   // log2(e)
#define LN2 0.6931471805599453f   // ln(2)

// ---- packed f32x2 + MUFU helpers (sm_103a) ----
__device__ __forceinline__ void ffma2(unsigned long long &d,
                                      unsigned long long a,
                                      unsigned long long b) {
    asm("fma.rn.f32x2 %0, %1, %2, %0;" : "+l"(d) : "l"(a), "l"(b));
}
__device__ __forceinline__ unsigned long long fadd2(unsigned long long a,
                                                    unsigned long long b) {
    unsigned long long d;
    asm("add.rn.f32x2 %0, %1, %2;" : "=l"(d) : "l"(a), "l"(b));
    return d;
}
__device__ __forceinline__ unsigned long long pack2(float lo, float hi) {
    unsigned long long d;
    asm("mov.b64 %0, {%1, %2};" : "=l"(d) : "f"(lo), "f"(hi));
    return d;
}
__device__ __forceinline__ void unpack2(unsigned long long v, float &lo, float &hi) {
    asm("mov.b64 {%0, %1}, %2;" : "=f"(lo), "=f"(hi) : "l"(v));
}
__device__ __forceinline__ float ex2(float x) {
    float r; asm("ex2.approx.f32 %0, %1;" : "=f"(r) : "f"(x)); return r;
}
__device__ __forceinline__ float lg2(float x) {
    float r; asm("lg2.approx.f32 %0, %1;" : "=f"(r) : "f"(x)); return r;
}

// One block (64 threads / 2 warps) per batch. Thread j owns tag-column j and
// holds A[i][j] = exp2(trans2[i][j]) in 32 packed f32x2 registers.
//
// LINEAR-DOMAIN recursion (no exp/log on the serial chain):
//   v_t[j] = m_t[j] * sum_i v_{t-1}[i] * A[i][j]
//   m_t[j] = ex2(emit2[t][j] - q_t),  q_t = lg2(v_{t-1}[0]) + C   (one-step-late
//            adaptive rescale; E0 is in smem right after the barrier, so the
//            lg2 -> ex2 for m_t runs IN PARALLEL with the GEMV).
//   R += q_t tracks the shift;  logZ = (R + lg2(sum_j v_last[j])) * ln2.
// Boundedness: v stays within exp2(+-~45) << fp32 range.
// Critical path per step: BAR -> LDS -> 32xFFMA2 -> FMUL -> STS -> BAR.
__global__ __launch_bounds__(64) void crf_fwd(
    const float* __restrict__ inputs,   // [B, T, N]
    const float* __restrict__ trans,    // [N, N]
    const int*   __restrict__ tags,     // [B, T]
    const int*   __restrict__ lens,     // [B]
    float*       __restrict__ out)      // [B + N*N]
{
    const int b    = blockIdx.x;
    const int j    = threadIdx.x;       // 0..63
    const int lane = j & 31;
    const int warp = j >> 5;

    // 68-float rows (272B = 17*16B) keep 16B alignment for v2.u64 loads.
    __shared__ __align__(16) float Esh[2][68];
    __shared__ float red[2];

    // Passthrough copy of transition_params (512 blocks x 8 elems = 4096).
    if (j < 8) {
        const int idx = b * 8 + j;
        out[B_ + idx] = trans[idx];
    }

    // Register-resident A[i][j] = exp2(trans[i][j] * L2E), packed over i.
    unsigned long long ETp[N_ / 2];
#pragma unroll
    for (int m = 0; m < N_ / 2; m++) {
        const float lo = ex2(trans[(2 * m) * N_ + j] * L2E);
        const float hi = ex2(trans[(2 * m + 1) * N_ + j] * L2E);
        ETp[m] = pack2(lo, hi);
    }

    const float* emit = inputs + (size_t)b * T_ * N_;
    const int len = lens[b];
    const int steps = (len > 1) ? (len - 1) : 0;   // last_index = max(0, len-1)

    // t = 0: v0[j] = exp2(emit2[0][j] - r0), r0 = emit2[0][0] (uniform LDG).
    const float r0 = __ldg(&emit[0]) * L2E;
    float R = r0;                                  // accumulated log2 shift
    float v = ex2(emit[j] * L2E - r0);
    Esh[0][j] = v;

    // Emission prefetch (distance 2), pre-scaled to log2 units.
    float ec = (steps >= 1) ? emit[N_ + j] * L2E : 0.0f;
    float en = (steps >= 2) ? emit[2 * N_ + j] * L2E : 0.0f;

    __syncthreads();

    for (int t = 1; t <= steps; t++) {
        const float e_nn = (t + 2 <= steps) ? emit[(t + 2) * N_ + j] * L2E : 0.0f;
        const int buf = (t - 1) & 1;

        // Off-chain: adaptive rescale from v_{t-1}[0] (available after barrier).
        const float E0 = Esh[buf][0];
        const float q  = lg2(E0) + 6.0f;           // C ~ lg2(N) centers the scale
        const float ms = ex2(ec - q);              // m_t[j]
        R += q;

        // GEMV: s_j = sum_i v[i] * A[i][j]. 16 broadcast LDS.128, 32 FFMA2,
        // 8 accumulators (depth-4 chains).
        const ulonglong2* ev = reinterpret_cast<const ulonglong2*>(&Esh[buf][0]);
        unsigned long long a0 = 0ull, a1 = 0ull, a2 = 0ull, a3 = 0ull;
        unsigned long long a4 = 0ull, a5 = 0ull, a6 = 0ull, a7 = 0ull;
#pragma unroll
        for (int m = 0; m < 4; m++) {
            const ulonglong2 p0 = ev[4 * m + 0];   // v[16m    .. 16m+3]
            const ulonglong2 p1 = ev[4 * m + 1];   // v[16m+4  .. 16m+7]
            const ulonglong2 p2 = ev[4 * m + 2];   // v[16m+8  .. 16m+11]
            const ulonglong2 p3 = ev[4 * m + 3];   // v[16m+12 .. 16m+15]
            ffma2(a0, p0.x, ETp[8 * m + 0]);
            ffma2(a1, p0.y, ETp[8 * m + 1]);
            ffma2(a2, p1.x, ETp[8 * m + 2]);
            ffma2(a3, p1.y, ETp[8 * m + 3]);
            ffma2(a4, p2.x, ETp[8 * m + 4]);
            ffma2(a5, p2.y, ETp[8 * m + 5]);
            ffma2(a6, p3.x, ETp[8 * m + 6]);
            ffma2(a7, p3.y, ETp[8 * m + 7]);
        }
        const unsigned long long sA =
            fadd2(fadd2(fadd2(a0, a1), fadd2(a2, a3)),
                  fadd2(fadd2(a4, a5), fadd2(a6, a7)));
        float slo, shi;
        unpack2(sA, slo, shi);

        v = ms * (slo + shi);                      // one FMUL on the chain
        Esh[buf ^ 1][j] = v;

        ec = en;
        en = e_nn;
        __syncthreads();                           // single barrier per step
    }

    // logZ = (R + lg2(sum_j v[j])) * ln2. v bounded -> direct linear sum is safe.
    float s = v;
#pragma unroll
    for (int off = 16; off; off >>= 1)
        s += __shfl_xor_sync(0xffffffffu, s, off);
    if (lane == 0) red[warp] = s;
    __syncthreads();
    const float logZ = (R + lg2(red[0] + red[1])) * LN2;

    // Sequence score: unary (t in [0,len)) + binary (t in [1,len)).
    const int* btags = tags + b * T_;
    float sc = 0.0f;
    for (int t = j; t < len; t += N_)
        sc += emit[t * N_ + btags[t]];
    for (int t = j + 1; t < len; t += N_)
        sc += trans[btags[t - 1] * N_ + btags[t]];

#pragma unroll
    for (int off = 16; off; off >>= 1)
        sc += __shfl_xor_sync(0xffffffffu, sc, off);
    __syncthreads();               // all logZ reads of red must complete first
    if (lane == 0) red[warp] = sc;
    __syncthreads();
    if (j == 0) out[b] = (red[0] + red[1]) - logZ;
}

extern "C" void kernel_launch(void* const* d_in, const int* in_sizes, int n_in,
                              void* d_out, int out_size) {
    const float* inputs = (const float*)d_in[0];   // [512, 512, 64] f32
    const float* trans  = (const float*)d_in[1];   // [64, 64] f32
    const int*   tags   = (const int*)d_in[2];     // [512, 512] i32
    const int*   lens   = (const int*)d_in[3];     // [512] i32
    float*       out    = (float*)d_out;           // [512 + 4096] f32

    crf_fwd<<<B_, N_>>>(inputs, trans, tags, lens, out);
}